// round 4
// baseline (speedup 1.0000x reference)
#include <cuda_runtime.h>
#include <math.h>

#define NMAX 50000
#define EMAX 800000
#define GMAX 1000
#define LEAK 0.01f
#define EPS  1e-5f
#define CDIV(a,b) (((a)+(b)-1)/(b))

typedef unsigned long long ull;

// ---------------- scratch ----------------------------------------------------
__device__ float g_bufA[NMAX*128];
__device__ float g_bufB[NMAX*128];
__device__ float g_bufC[NMAX*128];
__device__ int   g_indeg[NMAX];
__device__ int   g_off[NMAX+1];
__device__ int   g_cur[NMAX];
__device__ int   g_csr[EMAX];
__device__ float g_dinv[NMAX];     // rsqrt(indeg+1)
__device__ float g_rcnt[NMAX];     // 1/max(indeg,1)
__device__ float g_colsum[256];    // L1:0..127  L2:128..191  L3:192..223
__device__ float g_colsq[256];
__device__ float g_scale[256];
__device__ float g_shift[256];
__device__ float g_pool[GMAX*32];

// ---------------- f32x2 helpers ----------------------------------------------
__device__ __forceinline__ ull ffma2(ull a, ull b, ull c) {
    ull d;
    asm("fma.rn.f32x2 %0, %1, %2, %3;" : "=l"(d) : "l"(a), "l"(b), "l"(c));
    return d;
}
__device__ __forceinline__ ull pack2(float x) {
    ull d;
    asm("mov.b64 %0, {%1, %1};" : "=l"(d) : "f"(x));
    return d;
}

// ---------------- degree / CSR ----------------------------------------------
__global__ void deg_kernel(const int* __restrict__ dst, int nE) {
    int e = blockIdx.x * blockDim.x + threadIdx.x;
    if (e < nE) atomicAdd(&g_indeg[dst[e]], 1);
}

__global__ void scan_kernel(int n) {
    __shared__ int part[1024];
    int tid = threadIdx.x;
    int chunk = CDIV(n, 1024);
    int start = tid * chunk;
    int end   = min(start + chunk, n);
    int s = 0;
    for (int i = start; i < end; i++) s += g_indeg[i];
    part[tid] = s;
    __syncthreads();
    for (int off = 1; off < 1024; off <<= 1) {
        int v = (tid >= off) ? part[tid - off] : 0;
        __syncthreads();
        part[tid] += v;
        __syncthreads();
    }
    int run = (tid > 0) ? part[tid - 1] : 0;
    for (int i = start; i < end; i++) {
        int d = g_indeg[i];
        g_off[i] = run;
        g_cur[i] = run;
        g_dinv[i] = rsqrtf((float)(d + 1));
        g_rcnt[i] = 1.0f / (float)(d > 0 ? d : 1);
        run += d;
    }
    if (end == n && start < n) g_off[n] = run;
}

__global__ void fill_csr_kernel(const int* __restrict__ src,
                                const int* __restrict__ dst, int nE) {
    int e = blockIdx.x * blockDim.x + threadIdx.x;
    if (e < nE) {
        int p = atomicAdd(&g_cur[dst[e]], 1);
        g_csr[p] = src[e];
    }
}

// ---------------- FFMA2 GEMM: K=128, M=128, epilogue * dinv[row] -------------
// block 128 thr; warp w owns rows [b*32 + w*8, +8); lane owns cols lane*4..+3.
__global__ void gemm2_128x128(const float* __restrict__ X, const float* __restrict__ W,
                              float* __restrict__ Y, int n) {
    const int K = 128, M = 128, BR = 32, PBR = 36;
    __shared__ float xs[K * PBR];
    int tid = threadIdx.x;
    int r0  = blockIdx.x * BR;
    for (int i = tid; i < BR * K; i += 128) {
        int r = i >> 7, k = i & 127;
        int row = r0 + r;
        xs[k * PBR + r] = (row < n) ? X[row * K + k] : 0.0f;
    }
    __syncthreads();
    int lane = tid & 31, wrp = tid >> 5;
    ull acc[4][4];
#pragma unroll
    for (int p = 0; p < 4; p++)
#pragma unroll
        for (int c = 0; c < 4; c++) acc[p][c] = 0ull;

    const float4* W4 = (const float4*)W;
#pragma unroll 2
    for (int k = 0; k < K; k++) {
        float4 w = W4[k * 32 + lane];
        ull w0 = pack2(w.x), w1 = pack2(w.y), w2 = pack2(w.z), w3 = pack2(w.w);
        const ulonglong2* xv = (const ulonglong2*)&xs[k * PBR + wrp * 8];
        ulonglong2 xa = xv[0];   // rows 0-3 of this warp's 8
        ulonglong2 xb = xv[1];   // rows 4-7
        acc[0][0]=ffma2(xa.x,w0,acc[0][0]); acc[0][1]=ffma2(xa.x,w1,acc[0][1]);
        acc[0][2]=ffma2(xa.x,w2,acc[0][2]); acc[0][3]=ffma2(xa.x,w3,acc[0][3]);
        acc[1][0]=ffma2(xa.y,w0,acc[1][0]); acc[1][1]=ffma2(xa.y,w1,acc[1][1]);
        acc[1][2]=ffma2(xa.y,w2,acc[1][2]); acc[1][3]=ffma2(xa.y,w3,acc[1][3]);
        acc[2][0]=ffma2(xb.x,w0,acc[2][0]); acc[2][1]=ffma2(xb.x,w1,acc[2][1]);
        acc[2][2]=ffma2(xb.x,w2,acc[2][2]); acc[2][3]=ffma2(xb.x,w3,acc[2][3]);
        acc[3][0]=ffma2(xb.y,w0,acc[3][0]); acc[3][1]=ffma2(xb.y,w1,acc[3][1]);
        acc[3][2]=ffma2(xb.y,w2,acc[3][2]); acc[3][3]=ffma2(xb.y,w3,acc[3][3]);
    }
#pragma unroll
    for (int p = 0; p < 4; p++) {
        float2 u0 = *(float2*)&acc[p][0];
        float2 u1 = *(float2*)&acc[p][1];
        float2 u2 = *(float2*)&acc[p][2];
        float2 u3 = *(float2*)&acc[p][3];
        int rlo = r0 + wrp * 8 + 2 * p;
        if (rlo < n) {
            float d = g_dinv[rlo];
            ((float4*)Y)[(rlo * M >> 2) + lane] =
                make_float4(u0.x * d, u1.x * d, u2.x * d, u3.x * d);
        }
        int rhi = rlo + 1;
        if (rhi < n) {
            float d = g_dinv[rhi];
            ((float4*)Y)[(rhi * M >> 2) + lane] =
                make_float4(u0.y * d, u1.y * d, u2.y * d, u3.y * d);
        }
    }
}

// ---------------- FFMA2 SAGE GEMM: Y = AGG@Wl + H@Wr  (K=128, M=64) ----------
// + column stats of Y at offset 128. block 128; lane owns cols lane*2..+1.
__global__ void sage_gemm2(const float* __restrict__ H, const float* __restrict__ AGG,
                           const float* __restrict__ Wl, const float* __restrict__ Wr,
                           float* __restrict__ Y, int n) {
    const int K = 128, M = 64, BR = 32, PBR = 36;
    __shared__ float hs[K * PBR];
    __shared__ float as[K * PBR];
    __shared__ float cs[M], cq[M];
    int tid = threadIdx.x;
    int r0  = blockIdx.x * BR;
    if (tid < M) { cs[tid] = 0.0f; cq[tid] = 0.0f; }
    for (int i = tid; i < BR * K; i += 128) {
        int r = i >> 7, k = i & 127;
        int row = r0 + r;
        hs[k * PBR + r] = (row < n) ? H[row * K + k] : 0.0f;
        as[k * PBR + r] = (row < n) ? AGG[row * K + k] : 0.0f;
    }
    __syncthreads();
    int lane = tid & 31, wrp = tid >> 5;
    ull acc[4][2];
#pragma unroll
    for (int p = 0; p < 4; p++) { acc[p][0] = 0ull; acc[p][1] = 0ull; }

    const float2* Wl2 = (const float2*)Wl;
    const float2* Wr2 = (const float2*)Wr;
#pragma unroll 2
    for (int k = 0; k < K; k++) {
        float2 wl = Wl2[k * 32 + lane];
        float2 wr = Wr2[k * 32 + lane];
        ull wl0 = pack2(wl.x), wl1 = pack2(wl.y);
        ull wr0 = pack2(wr.x), wr1 = pack2(wr.y);
        const ulonglong2* hv = (const ulonglong2*)&hs[k * PBR + wrp * 8];
        const ulonglong2* av = (const ulonglong2*)&as[k * PBR + wrp * 8];
        ulonglong2 ha = hv[0], hb = hv[1];
        ulonglong2 aa = av[0], ab = av[1];
        acc[0][0]=ffma2(aa.x,wl0,ffma2(ha.x,wr0,acc[0][0]));
        acc[0][1]=ffma2(aa.x,wl1,ffma2(ha.x,wr1,acc[0][1]));
        acc[1][0]=ffma2(aa.y,wl0,ffma2(ha.y,wr0,acc[1][0]));
        acc[1][1]=ffma2(aa.y,wl1,ffma2(ha.y,wr1,acc[1][1]));
        acc[2][0]=ffma2(ab.x,wl0,ffma2(hb.x,wr0,acc[2][0]));
        acc[2][1]=ffma2(ab.x,wl1,ffma2(hb.x,wr1,acc[2][1]));
        acc[3][0]=ffma2(ab.y,wl0,ffma2(hb.y,wr0,acc[3][0]));
        acc[3][1]=ffma2(ab.y,wl1,ffma2(hb.y,wr1,acc[3][1]));
    }
    float ps0 = 0.f, pq0 = 0.f, ps1 = 0.f, pq1 = 0.f;
#pragma unroll
    for (int p = 0; p < 4; p++) {
        float2 u0 = *(float2*)&acc[p][0];
        float2 u1 = *(float2*)&acc[p][1];
        int rlo = r0 + wrp * 8 + 2 * p;
        if (rlo < n) {
            ((float2*)Y)[(rlo * M >> 1) + lane] = make_float2(u0.x, u1.x);
            ps0 += u0.x; pq0 += u0.x * u0.x;
            ps1 += u1.x; pq1 += u1.x * u1.x;
        }
        int rhi = rlo + 1;
        if (rhi < n) {
            ((float2*)Y)[(rhi * M >> 1) + lane] = make_float2(u0.y, u1.y);
            ps0 += u0.y; pq0 += u0.y * u0.y;
            ps1 += u1.y; pq1 += u1.y * u1.y;
        }
    }
    atomicAdd(&cs[lane * 2 + 0], ps0); atomicAdd(&cq[lane * 2 + 0], pq0);
    atomicAdd(&cs[lane * 2 + 1], ps1); atomicAdd(&cq[lane * 2 + 1], pq1);
    __syncthreads();
    if (tid < M) {
        atomicAdd(&g_colsum[128 + tid], cs[tid]);
        atomicAdd(&g_colsq[128 + tid],  cq[tid]);
    }
}

// ---------------- small GEMM (M=32): Y = lrelu(bn(X)) @ W, * dinv ------------
template <int K, int M, int ROWS, int OFF>
__global__ void gemm_small(const float* __restrict__ X, const float* __restrict__ W,
                           float* __restrict__ Y, int n) {
    const int RG  = 128 / M;
    const int BR  = RG * ROWS;
    const int PBR = BR + 4;
    __shared__ float xs[K * PBR];
    int tid = threadIdx.x;
    int r0  = blockIdx.x * BR;
    for (int i = tid; i < BR * K; i += 128) {
        int r = i / K, k = i % K;
        int row = r0 + r;
        float v = (row < n) ? X[row * K + k] : 0.0f;
        v = fmaf(v, g_scale[OFF + k], g_shift[OFF + k]);
        v = (v >= 0.0f) ? v : LEAK * v;
        xs[k * PBR + r] = v;
    }
    __syncthreads();
    int col = tid % M;
    int rg  = tid / M;
    float acc[ROWS];
#pragma unroll
    for (int r = 0; r < ROWS; r++) acc[r] = 0.0f;
#pragma unroll 4
    for (int k = 0; k < K; k++) {
        float w = W[k * M + col];
        const float4* xv = (const float4*)&xs[k * PBR + rg * ROWS];
#pragma unroll
        for (int r4 = 0; r4 < ROWS / 4; r4++) {
            float4 xx = xv[r4];
            acc[r4*4+0] = fmaf(xx.x, w, acc[r4*4+0]);
            acc[r4*4+1] = fmaf(xx.y, w, acc[r4*4+1]);
            acc[r4*4+2] = fmaf(xx.z, w, acc[r4*4+2]);
            acc[r4*4+3] = fmaf(xx.w, w, acc[r4*4+3]);
        }
    }
#pragma unroll
    for (int r = 0; r < ROWS; r++) {
        int row = r0 + rg * ROWS + r;
        if (row < n) Y[row * M + col] = acc[r] * g_dinv[row];
    }
}

// ---------------- CSR gathers ------------------------------------------------
// Layer-1 GCN gather (F=128) + column stats at offset 0.
__global__ void gather128_gcn_stats(const float* __restrict__ Hin,
                                    float* __restrict__ Hout, int n) {
    __shared__ float cs[128], cq[128];
    int tid = threadIdx.x;
    if (tid < 128) { cs[tid] = 0.0f; cq[tid] = 0.0f; }
    __syncthreads();
    int warp = (blockIdx.x * 512 + tid) >> 5;
    int lane = tid & 31;
    if (warp < n) {
        int beg = g_off[warp], end = g_off[warp + 1];
        const float4* H4 = (const float4*)Hin;
        float4 acc = H4[warp * 32 + lane];
#pragma unroll 4
        for (int e = beg; e < end; e++) {
            int s = __ldg(&g_csr[e]);
            float4 v = H4[s * 32 + lane];
            acc.x += v.x; acc.y += v.y; acc.z += v.z; acc.w += v.w;
        }
        float sc = g_dinv[warp];
        acc.x *= sc; acc.y *= sc; acc.z *= sc; acc.w *= sc;
        ((float4*)Hout)[warp * 32 + lane] = acc;
        int c = lane * 4;
        atomicAdd(&cs[c+0], acc.x); atomicAdd(&cq[c+0], acc.x*acc.x);
        atomicAdd(&cs[c+1], acc.y); atomicAdd(&cq[c+1], acc.y*acc.y);
        atomicAdd(&cs[c+2], acc.z); atomicAdd(&cq[c+2], acc.z*acc.z);
        atomicAdd(&cs[c+3], acc.w); atomicAdd(&cq[c+3], acc.w*acc.w);
    }
    __syncthreads();
    if (tid < 128) {
        atomicAdd(&g_colsum[tid], cs[tid]);
        atomicAdd(&g_colsq[tid],  cq[tid]);
    }
}

// SAGE mean gather (F=128), plain.
__global__ void gather128_mean(const float* __restrict__ Hin,
                               float* __restrict__ Hout, int n) {
    int warp = (blockIdx.x * blockDim.x + threadIdx.x) >> 5;
    int lane = threadIdx.x & 31;
    if (warp >= n) return;
    int beg = g_off[warp], end = g_off[warp + 1];
    const float4* H4 = (const float4*)Hin;
    float4 acc = make_float4(0.f, 0.f, 0.f, 0.f);
#pragma unroll 4
    for (int e = beg; e < end; e++) {
        int s = __ldg(&g_csr[e]);
        float4 v = H4[s * 32 + lane];
        acc.x += v.x; acc.y += v.y; acc.z += v.z; acc.w += v.w;
    }
    float r = g_rcnt[warp];
    acc.x *= r; acc.y *= r; acc.z *= r; acc.w *= r;
    ((float4*)Hout)[warp * 32 + lane] = acc;
}

// F=32 GCN gather; optional stats at offset 192.
template <int STATS>
__global__ void gather32_kernel(const float* __restrict__ Hin,
                                float* __restrict__ Hout, int n) {
    __shared__ float cs[32], cq[32];
    int tid = threadIdx.x;
    if (STATS) {
        if (tid < 32) { cs[tid] = 0.0f; cq[tid] = 0.0f; }
        __syncthreads();
    }
    int warp = (blockIdx.x * 512 + tid) >> 5;
    int lane = tid & 31;
    if (warp < n) {
        int beg = g_off[warp], end = g_off[warp + 1];
        float acc = Hin[warp * 32 + lane];
#pragma unroll 4
        for (int e = beg; e < end; e++) {
            int s = __ldg(&g_csr[e]);
            acc += Hin[s * 32 + lane];
        }
        acc *= g_dinv[warp];
        Hout[warp * 32 + lane] = acc;
        if (STATS) {
            atomicAdd(&cs[lane], acc);
            atomicAdd(&cq[lane], acc * acc);
        }
    }
    if (STATS) {
        __syncthreads();
        if (tid < 32) {
            atomicAdd(&g_colsum[192 + tid], cs[tid]);
            atomicAdd(&g_colsq[192 + tid],  cq[tid]);
        }
    }
}

// ---------------- BN finalize / apply ----------------------------------------
__global__ void bn_finalize_kernel(const float* __restrict__ gamma,
                                   const float* __restrict__ beta, int off, float invn) {
    int c = threadIdx.x;
    float m   = g_colsum[off + c] * invn;
    float var = g_colsq[off + c] * invn - m * m;
    float sc  = gamma[c] * rsqrtf(var + EPS);
    g_scale[off + c] = sc;
    g_shift[off + c] = beta[c] - m * sc;
}

__global__ void bn_apply128(const float* __restrict__ X, float* __restrict__ Y,
                            long long total4) {
    long long i = (long long)blockIdx.x * blockDim.x + threadIdx.x;
    if (i < total4) {
        int c = (int)(i & 31);
        float4 v = ((const float4*)X)[i];
        float4 sc = ((const float4*)g_scale)[c];
        float4 sh = ((const float4*)g_shift)[c];
        float a;
        a = fmaf(v.x, sc.x, sh.x); v.x = (a >= 0.f) ? a : LEAK * a;
        a = fmaf(v.y, sc.y, sh.y); v.y = (a >= 0.f) ? a : LEAK * a;
        a = fmaf(v.z, sc.z, sh.z); v.z = (a >= 0.f) ? a : LEAK * a;
        a = fmaf(v.w, sc.w, sh.w); v.w = (a >= 0.f) ? a : LEAK * a;
        ((float4*)Y)[i] = v;
    }
}

// ---------------- pool + link ------------------------------------------------
__global__ void pool_kernel(const float* __restrict__ H, const int* __restrict__ batch,
                            const float* __restrict__ b4, int n) {
    int t = blockIdx.x * blockDim.x + threadIdx.x;
    int node = t / 8, j = t % 8;
    if (node >= n) return;
    int g = batch[node];
    float4 v = ((const float4*)H)[node * 8 + j];
    float4 bb = ((const float4*)b4)[j];
    v.x += bb.x; v.y += bb.y; v.z += bb.z; v.w += bb.w;
    float4* p = ((float4*)g_pool) + g * 8 + j;
    asm volatile("red.global.add.v4.f32 [%0], {%1,%2,%3,%4};"
                 :: "l"(p), "f"(v.x), "f"(v.y), "f"(v.z), "f"(v.w) : "memory");
}

__global__ void link_kernel(const int* __restrict__ li, float* __restrict__ out, int L) {
    int w = (blockIdx.x * blockDim.x + threadIdx.x) / 32;
    int lane = threadIdx.x & 31;
    if (w >= L) return;
    int a = li[w], b = li[L + w];
    float v = g_pool[a * 32 + lane] * g_pool[b * 32 + lane];
#pragma unroll
    for (int off = 16; off > 0; off >>= 1)
        v += __shfl_xor_sync(0xFFFFFFFFu, v, off);
    if (lane == 0) out[w] = 1.0f / (1.0f + expf(-v));
}

// ---------------- launch -----------------------------------------------------
extern "C" void kernel_launch(void* const* d_in, const int* in_sizes, int n_in,
                              void* d_out, int out_size) {
    int base = 4;
    if (n_in >= 20 && in_sizes[4] == 1) base = 5;

    const float* x    = (const float*)d_in[0];
    const int*   ei   = (const int*)d_in[1];
    const int*   batch= (const int*)d_in[2];
    const int*   li   = (const int*)d_in[3];
    const float* W1   = (const float*)d_in[base + 0];
    const float* g1   = (const float*)d_in[base + 2];
    const float* be1  = (const float*)d_in[base + 3];
    const float* Wl2  = (const float*)d_in[base + 4];
    const float* Wr2  = (const float*)d_in[base + 6];
    const float* g2   = (const float*)d_in[base + 7];
    const float* be2  = (const float*)d_in[base + 8];
    const float* W3   = (const float*)d_in[base + 9];
    const float* g3   = (const float*)d_in[base + 11];
    const float* be3  = (const float*)d_in[base + 12];
    const float* W4   = (const float*)d_in[base + 13];
    const float* b4   = (const float*)d_in[base + 14];
    float* out = (float*)d_out;

    const int N = in_sizes[0] / 128;
    const int E = in_sizes[1] / 2;
    const int L = in_sizes[3] / 2;
    const int* src = ei;
    const int* dst = ei + E;
    const float invN = 1.0f / (float)N;

    float *bufA, *bufB, *bufC, *poolp, *colsum, *colsq;
    int* indeg;
    cudaGetSymbolAddress((void**)&bufA,   g_bufA);
    cudaGetSymbolAddress((void**)&bufB,   g_bufB);
    cudaGetSymbolAddress((void**)&bufC,   g_bufC);
    cudaGetSymbolAddress((void**)&indeg,  g_indeg);
    cudaGetSymbolAddress((void**)&poolp,  g_pool);
    cudaGetSymbolAddress((void**)&colsum, g_colsum);
    cudaGetSymbolAddress((void**)&colsq,  g_colsq);

    // ---- setup ----
    cudaMemsetAsync(indeg,  0, N * sizeof(int));
    cudaMemsetAsync(colsum, 0, 256 * sizeof(float));
    cudaMemsetAsync(colsq,  0, 256 * sizeof(float));
    cudaMemsetAsync(poolp,  0, (size_t)GMAX * 32 * sizeof(float));
    deg_kernel<<<CDIV(E, 256), 256>>>(dst, E);
    scan_kernel<<<1, 1024>>>(N);
    fill_csr_kernel<<<CDIV(E, 256), 256>>>(src, dst, E);

    // ---- Layer 1: GCN(128->128); stats fused in gather; apply once ----
    gemm2_128x128<<<CDIV(N, 32), 128>>>(x, W1, bufA, N);
    gather128_gcn_stats<<<CDIV(N * 32, 512), 512>>>(bufA, bufB, N);
    bn_finalize_kernel<<<1, 128>>>(g1, be1, 0, invN);
    bn_apply128<<<CDIV((long long)N * 32, 256), 256>>>(bufB, bufA, (long long)N * 32); // h1

    // ---- Layer 2: SAGE(128->64); stats fused in GEMM epilogue ----
    gather128_mean<<<CDIV(N * 32, 256), 256>>>(bufA, bufC, N);
    sage_gemm2<<<CDIV(N, 32), 128>>>(bufA, bufC, Wl2, Wr2, bufB, N);
    bn_finalize_kernel<<<1, 64>>>(g2, be2, 128, invN);

    // ---- Layer 3: GCN(64->32); BN2 applied on GEMM load, stats3 in gather ----
    gemm_small<64, 32, 8, 128><<<CDIV(N, 32), 128>>>(bufB, W3, bufC, N);
    gather32_kernel<1><<<CDIV(N * 32, 512), 512>>>(bufC, bufA, N);
    bn_finalize_kernel<<<1, 32>>>(g3, be3, 192, invN);

    // ---- Layer 4: GCN(32->32); BN3 applied on GEMM load; b4 folded into pool ----
    gemm_small<32, 32, 8, 192><<<CDIV(N, 32), 128>>>(bufA, W4, bufC, N);
    gather32_kernel<0><<<CDIV(N * 32, 512), 512>>>(bufC, bufB, N);

    // ---- pool + link ----
    pool_kernel<<<CDIV(N * 8, 256), 256>>>(bufB, batch, b4, N);
    link_kernel<<<CDIV(L * 32, 256), 256>>>(li, out, L);
}

// round 5
// speedup vs baseline: 1.3448x; 1.3448x over previous
#include <cuda_runtime.h>
#include <math.h>

#define NMAX 50000
#define EMAX 800000
#define GMAX 1000
#define LEAK 0.01f
#define EPS  1e-5f
#define CDIV(a,b) (((a)+(b)-1)/(b))

// ---------------- scratch ----------------------------------------------------
__device__ float g_bufA[NMAX*128];
__device__ float g_bufB[NMAX*128];
__device__ float g_bufC[NMAX*128];
__device__ int   g_indeg[NMAX];
__device__ int   g_off[NMAX+1];
__device__ int   g_cur[NMAX];
__device__ int   g_csr[EMAX];
__device__ float g_dinv[NMAX];     // rsqrt(indeg+1)
__device__ float g_rcnt[NMAX];     // 1/max(indeg,1)
__device__ float g_colsum[256];    // L1:0..127  L2:128..191  L3:192..223
__device__ float g_colsq[256];
__device__ float g_scale[256];
__device__ float g_shift[256];
__device__ float g_pool[GMAX*32];

// ---------------- degree / CSR ----------------------------------------------
__global__ void deg_kernel(const int* __restrict__ dst, int nE) {
    int e = blockIdx.x * blockDim.x + threadIdx.x;
    if (e < nE) atomicAdd(&g_indeg[dst[e]], 1);
}

__global__ void scan_kernel(int n) {
    __shared__ int part[1024];
    int tid = threadIdx.x;
    int chunk = CDIV(n, 1024);
    int start = tid * chunk;
    int end   = min(start + chunk, n);
    int s = 0;
    for (int i = start; i < end; i++) s += g_indeg[i];
    part[tid] = s;
    __syncthreads();
    for (int off = 1; off < 1024; off <<= 1) {
        int v = (tid >= off) ? part[tid - off] : 0;
        __syncthreads();
        part[tid] += v;
        __syncthreads();
    }
    int run = (tid > 0) ? part[tid - 1] : 0;
    for (int i = start; i < end; i++) {
        int d = g_indeg[i];
        g_off[i] = run;
        g_cur[i] = run;
        g_dinv[i] = rsqrtf((float)(d + 1));
        g_rcnt[i] = 1.0f / (float)(d > 0 ? d : 1);
        run += d;
    }
    if (end == n && start < n) g_off[n] = run;
}

__global__ void fill_csr_kernel(const int* __restrict__ src,
                                const int* __restrict__ dst, int nE) {
    int e = blockIdx.x * blockDim.x + threadIdx.x;
    if (e < nE) {
        int p = atomicAdd(&g_cur[dst[e]], 1);
        g_csr[p] = src[e];
    }
}

// ---------------- big GEMM: Y[n,128] = X[n,128] @ W, * dinv[row] -------------
// block 128 threads, 16 rows/block, thread owns one output column.
__global__ void gemm1_kernel(const float* __restrict__ X, const float* __restrict__ W,
                             float* __restrict__ Y, int n) {
    const int K = 128, M = 128, BR = 16, PBR = 20;
    __shared__ float xs[K * PBR];
    int tid = threadIdx.x;
    int r0  = blockIdx.x * BR;
    for (int i = tid; i < BR * K; i += 128) {
        int r = i >> 7, k = i & 127;
        int row = r0 + r;
        xs[k * PBR + r] = (row < n) ? X[row * K + k] : 0.0f;
    }
    __syncthreads();
    float acc[BR];
#pragma unroll
    for (int r = 0; r < BR; r++) acc[r] = 0.0f;
#pragma unroll 4
    for (int k = 0; k < K; k++) {
        float w = W[k * M + tid];
        const float4* xv = (const float4*)&xs[k * PBR];
#pragma unroll
        for (int r4 = 0; r4 < BR / 4; r4++) {
            float4 xx = xv[r4];
            acc[r4*4+0] = fmaf(xx.x, w, acc[r4*4+0]);
            acc[r4*4+1] = fmaf(xx.y, w, acc[r4*4+1]);
            acc[r4*4+2] = fmaf(xx.z, w, acc[r4*4+2]);
            acc[r4*4+3] = fmaf(xx.w, w, acc[r4*4+3]);
        }
    }
#pragma unroll
    for (int r = 0; r < BR; r++) {
        int row = r0 + r;
        if (row < n) Y[row * M + tid] = acc[r] * g_dinv[row];
    }
}

// ---------------- SAGE GEMM: Y = AGG@Wl + H@Wr (K=128, M=64) + stats@128 -----
__global__ void sage_gemm_kernel(const float* __restrict__ H, const float* __restrict__ AGG,
                                 const float* __restrict__ Wl, const float* __restrict__ Wr,
                                 float* __restrict__ Y, int n) {
    const int K = 128, M = 64, ROWS = 8, BR = 16, PBR = 20;
    __shared__ float hs[K * PBR];
    __shared__ float as[K * PBR];
    __shared__ float cs[M], cq[M];
    int tid = threadIdx.x;
    int r0  = blockIdx.x * BR;
    if (tid < M) { cs[tid] = 0.0f; cq[tid] = 0.0f; }
    for (int i = tid; i < BR * K; i += 128) {
        int r = i >> 7, k = i & 127;
        int row = r0 + r;
        float hv = 0.0f, av = 0.0f;
        if (row < n) { hv = H[row * K + k]; av = AGG[row * K + k]; }
        hs[k * PBR + r] = hv;
        as[k * PBR + r] = av;
    }
    __syncthreads();
    int col = tid & 63;
    int rg  = tid >> 6;
    float acc[ROWS];
#pragma unroll
    for (int r = 0; r < ROWS; r++) acc[r] = 0.0f;
#pragma unroll 2
    for (int k = 0; k < K; k++) {
        float wl = Wl[k * M + col];
        float wr = Wr[k * M + col];
        const float4* hv = (const float4*)&hs[k * PBR + rg * ROWS];
        const float4* av = (const float4*)&as[k * PBR + rg * ROWS];
#pragma unroll
        for (int r4 = 0; r4 < ROWS / 4; r4++) {
            float4 hh = hv[r4];
            float4 aa = av[r4];
            acc[r4*4+0] = fmaf(aa.x, wl, fmaf(hh.x, wr, acc[r4*4+0]));
            acc[r4*4+1] = fmaf(aa.y, wl, fmaf(hh.y, wr, acc[r4*4+1]));
            acc[r4*4+2] = fmaf(aa.z, wl, fmaf(hh.z, wr, acc[r4*4+2]));
            acc[r4*4+3] = fmaf(aa.w, wl, fmaf(hh.w, wr, acc[r4*4+3]));
        }
    }
    float ps = 0.0f, pq = 0.0f;
#pragma unroll
    for (int r = 0; r < ROWS; r++) {
        int row = r0 + rg * ROWS + r;
        if (row < n) {
            Y[row * M + col] = acc[r];
            ps += acc[r];
            pq += acc[r] * acc[r];
        }
    }
    atomicAdd(&cs[col], ps);
    atomicAdd(&cq[col], pq);
    __syncthreads();
    if (tid < M) {
        atomicAdd(&g_colsum[128 + tid], cs[tid]);
        atomicAdd(&g_colsq[128 + tid],  cq[tid]);
    }
}

// ---------------- small GEMM (M=32): Y = lrelu(bn(X)) @ W, * dinv ------------
template <int K, int M, int ROWS, int OFF>
__global__ void gemm_small(const float* __restrict__ X, const float* __restrict__ W,
                           float* __restrict__ Y, int n) {
    const int RG  = 128 / M;
    const int BR  = RG * ROWS;
    const int PBR = BR + 4;
    __shared__ float xs[K * PBR];
    int tid = threadIdx.x;
    int r0  = blockIdx.x * BR;
    for (int i = tid; i < BR * K; i += 128) {
        int r = i / K, k = i % K;
        int row = r0 + r;
        float v = (row < n) ? X[row * K + k] : 0.0f;
        v = fmaf(v, g_scale[OFF + k], g_shift[OFF + k]);
        v = (v >= 0.0f) ? v : LEAK * v;
        xs[k * PBR + r] = v;
    }
    __syncthreads();
    int col = tid % M;
    int rg  = tid / M;
    float acc[ROWS];
#pragma unroll
    for (int r = 0; r < ROWS; r++) acc[r] = 0.0f;
#pragma unroll 4
    for (int k = 0; k < K; k++) {
        float w = W[k * M + col];
        const float4* xv = (const float4*)&xs[k * PBR + rg * ROWS];
#pragma unroll
        for (int r4 = 0; r4 < ROWS / 4; r4++) {
            float4 xx = xv[r4];
            acc[r4*4+0] = fmaf(xx.x, w, acc[r4*4+0]);
            acc[r4*4+1] = fmaf(xx.y, w, acc[r4*4+1]);
            acc[r4*4+2] = fmaf(xx.z, w, acc[r4*4+2]);
            acc[r4*4+3] = fmaf(xx.w, w, acc[r4*4+3]);
        }
    }
#pragma unroll
    for (int r = 0; r < ROWS; r++) {
        int row = r0 + rg * ROWS + r;
        if (row < n) Y[row * M + col] = acc[r] * g_dinv[row];
    }
}

// ---------------- CSR gathers ------------------------------------------------
// Layer-1 GCN gather (F=128) + column stats at offset 0.
__global__ void gather128_gcn_stats(const float* __restrict__ Hin,
                                    float* __restrict__ Hout, int n) {
    __shared__ float cs[128], cq[128];
    int tid = threadIdx.x;
    if (tid < 128) { cs[tid] = 0.0f; cq[tid] = 0.0f; }
    __syncthreads();
    int warp = (blockIdx.x * 512 + tid) >> 5;
    int lane = tid & 31;
    if (warp < n) {
        int beg = g_off[warp], end = g_off[warp + 1];
        const float4* H4 = (const float4*)Hin;
        float4 acc = H4[warp * 32 + lane];
#pragma unroll 4
        for (int e = beg; e < end; e++) {
            int s = __ldg(&g_csr[e]);
            float4 v = H4[s * 32 + lane];
            acc.x += v.x; acc.y += v.y; acc.z += v.z; acc.w += v.w;
        }
        float sc = g_dinv[warp];
        acc.x *= sc; acc.y *= sc; acc.z *= sc; acc.w *= sc;
        ((float4*)Hout)[warp * 32 + lane] = acc;
        int c = lane * 4;
        atomicAdd(&cs[c+0], acc.x); atomicAdd(&cq[c+0], acc.x*acc.x);
        atomicAdd(&cs[c+1], acc.y); atomicAdd(&cq[c+1], acc.y*acc.y);
        atomicAdd(&cs[c+2], acc.z); atomicAdd(&cq[c+2], acc.z*acc.z);
        atomicAdd(&cs[c+3], acc.w); atomicAdd(&cq[c+3], acc.w*acc.w);
    }
    __syncthreads();
    if (tid < 128) {
        atomicAdd(&g_colsum[tid], cs[tid]);
        atomicAdd(&g_colsq[tid],  cq[tid]);
    }
}

// SAGE mean gather (F=128), plain.
__global__ void gather128_mean(const float* __restrict__ Hin,
                               float* __restrict__ Hout, int n) {
    int warp = (blockIdx.x * blockDim.x + threadIdx.x) >> 5;
    int lane = threadIdx.x & 31;
    if (warp >= n) return;
    int beg = g_off[warp], end = g_off[warp + 1];
    const float4* H4 = (const float4*)Hin;
    float4 acc = make_float4(0.f, 0.f, 0.f, 0.f);
#pragma unroll 4
    for (int e = beg; e < end; e++) {
        int s = __ldg(&g_csr[e]);
        float4 v = H4[s * 32 + lane];
        acc.x += v.x; acc.y += v.y; acc.z += v.z; acc.w += v.w;
    }
    float r = g_rcnt[warp];
    acc.x *= r; acc.y *= r; acc.z *= r; acc.w *= r;
    ((float4*)Hout)[warp * 32 + lane] = acc;
}

// F=32 GCN gather; optional stats at offset 192.
template <int STATS>
__global__ void gather32_kernel(const float* __restrict__ Hin,
                                float* __restrict__ Hout, int n) {
    __shared__ float cs[32], cq[32];
    int tid = threadIdx.x;
    if (STATS) {
        if (tid < 32) { cs[tid] = 0.0f; cq[tid] = 0.0f; }
        __syncthreads();
    }
    int warp = (blockIdx.x * 512 + tid) >> 5;
    int lane = tid & 31;
    if (warp < n) {
        int beg = g_off[warp], end = g_off[warp + 1];
        float acc = Hin[warp * 32 + lane];
#pragma unroll 4
        for (int e = beg; e < end; e++) {
            int s = __ldg(&g_csr[e]);
            acc += Hin[s * 32 + lane];
        }
        acc *= g_dinv[warp];
        Hout[warp * 32 + lane] = acc;
        if (STATS) {
            atomicAdd(&cs[lane], acc);
            atomicAdd(&cq[lane], acc * acc);
        }
    }
    if (STATS) {
        __syncthreads();
        if (tid < 32) {
            atomicAdd(&g_colsum[192 + tid], cs[tid]);
            atomicAdd(&g_colsq[192 + tid],  cq[tid]);
        }
    }
}

// ---------------- BN finalize / apply ----------------------------------------
__global__ void bn_finalize_kernel(const float* __restrict__ gamma,
                                   const float* __restrict__ beta, int off, float invn) {
    int c = threadIdx.x;
    float m   = g_colsum[off + c] * invn;
    float var = g_colsq[off + c] * invn - m * m;
    float sc  = gamma[c] * rsqrtf(var + EPS);
    g_scale[off + c] = sc;
    g_shift[off + c] = beta[c] - m * sc;
}

__global__ void bn_apply128(const float* __restrict__ X, float* __restrict__ Y,
                            long long total4) {
    long long i = (long long)blockIdx.x * blockDim.x + threadIdx.x;
    if (i < total4) {
        int c = (int)(i & 31);
        float4 v = ((const float4*)X)[i];
        float4 sc = ((const float4*)g_scale)[c];
        float4 sh = ((const float4*)g_shift)[c];
        float a;
        a = fmaf(v.x, sc.x, sh.x); v.x = (a >= 0.f) ? a : LEAK * a;
        a = fmaf(v.y, sc.y, sh.y); v.y = (a >= 0.f) ? a : LEAK * a;
        a = fmaf(v.z, sc.z, sh.z); v.z = (a >= 0.f) ? a : LEAK * a;
        a = fmaf(v.w, sc.w, sh.w); v.w = (a >= 0.f) ? a : LEAK * a;
        ((float4*)Y)[i] = v;
    }
}

// ---------------- pool + link ------------------------------------------------
__global__ void pool_kernel(const float* __restrict__ H, const int* __restrict__ batch,
                            const float* __restrict__ b4, int n) {
    int t = blockIdx.x * blockDim.x + threadIdx.x;
    int node = t / 8, j = t % 8;
    if (node >= n) return;
    int g = batch[node];
    float4 v = ((const float4*)H)[node * 8 + j];
    float4 bb = ((const float4*)b4)[j];
    v.x += bb.x; v.y += bb.y; v.z += bb.z; v.w += bb.w;
    float4* p = ((float4*)g_pool) + g * 8 + j;
    asm volatile("red.global.add.v4.f32 [%0], {%1,%2,%3,%4};"
                 :: "l"(p), "f"(v.x), "f"(v.y), "f"(v.z), "f"(v.w) : "memory");
}

__global__ void link_kernel(const int* __restrict__ li, float* __restrict__ out, int L) {
    int w = (blockIdx.x * blockDim.x + threadIdx.x) / 32;
    int lane = threadIdx.x & 31;
    if (w >= L) return;
    int a = li[w], b = li[L + w];
    float v = g_pool[a * 32 + lane] * g_pool[b * 32 + lane];
#pragma unroll
    for (int off = 16; off > 0; off >>= 1)
        v += __shfl_xor_sync(0xFFFFFFFFu, v, off);
    if (lane == 0) out[w] = 1.0f / (1.0f + expf(-v));
}

// ---------------- launch -----------------------------------------------------
extern "C" void kernel_launch(void* const* d_in, const int* in_sizes, int n_in,
                              void* d_out, int out_size) {
    int base = 4;
    if (n_in >= 20 && in_sizes[4] == 1) base = 5;

    const float* x    = (const float*)d_in[0];
    const int*   ei   = (const int*)d_in[1];
    const int*   batch= (const int*)d_in[2];
    const int*   li   = (const int*)d_in[3];
    const float* W1   = (const float*)d_in[base + 0];
    const float* g1   = (const float*)d_in[base + 2];
    const float* be1  = (const float*)d_in[base + 3];
    const float* Wl2  = (const float*)d_in[base + 4];
    const float* Wr2  = (const float*)d_in[base + 6];
    const float* g2   = (const float*)d_in[base + 7];
    const float* be2  = (const float*)d_in[base + 8];
    const float* W3   = (const float*)d_in[base + 9];
    const float* g3   = (const float*)d_in[base + 11];
    const float* be3  = (const float*)d_in[base + 12];
    const float* W4   = (const float*)d_in[base + 13];
    const float* b4   = (const float*)d_in[base + 14];
    float* out = (float*)d_out;

    const int N = in_sizes[0] / 128;
    const int E = in_sizes[1] / 2;
    const int L = in_sizes[3] / 2;
    const int* src = ei;
    const int* dst = ei + E;
    const float invN = 1.0f / (float)N;

    float *bufA, *bufB, *bufC, *poolp, *colsum, *colsq;
    int* indeg;
    cudaGetSymbolAddress((void**)&bufA,   g_bufA);
    cudaGetSymbolAddress((void**)&bufB,   g_bufB);
    cudaGetSymbolAddress((void**)&bufC,   g_bufC);
    cudaGetSymbolAddress((void**)&indeg,  g_indeg);
    cudaGetSymbolAddress((void**)&poolp,  g_pool);
    cudaGetSymbolAddress((void**)&colsum, g_colsum);
    cudaGetSymbolAddress((void**)&colsq,  g_colsq);

    // ---- setup ----
    cudaMemsetAsync(indeg,  0, N * sizeof(int));
    cudaMemsetAsync(colsum, 0, 256 * sizeof(float));
    cudaMemsetAsync(colsq,  0, 256 * sizeof(float));
    cudaMemsetAsync(poolp,  0, (size_t)GMAX * 32 * sizeof(float));
    deg_kernel<<<CDIV(E, 256), 256>>>(dst, E);
    scan_kernel<<<1, 1024>>>(N);
    fill_csr_kernel<<<CDIV(E, 256), 256>>>(src, dst, E);

    // ---- Layer 1: GCN(128->128); stats fused in gather; apply once ----
    gemm1_kernel<<<CDIV(N, 16), 128>>>(x, W1, bufA, N);
    gather128_gcn_stats<<<CDIV(N * 32, 512), 512>>>(bufA, bufB, N);
    bn_finalize_kernel<<<1, 128>>>(g1, be1, 0, invN);
    bn_apply128<<<CDIV((long long)N * 32, 256), 256>>>(bufB, bufA, (long long)N * 32); // h1

    // ---- Layer 2: SAGE(128->64); stats fused in GEMM epilogue ----
    gather128_mean<<<CDIV(N * 32, 256), 256>>>(bufA, bufC, N);
    sage_gemm_kernel<<<CDIV(N, 16), 128>>>(bufA, bufC, Wl2, Wr2, bufB, N);
    bn_finalize_kernel<<<1, 64>>>(g2, be2, 128, invN);

    // ---- Layer 3: GCN(64->32); BN2 applied on GEMM load, stats3 in gather ----
    gemm_small<64, 32, 8, 128><<<CDIV(N, 32), 128>>>(bufB, W3, bufC, N);
    gather32_kernel<1><<<CDIV(N * 32, 512), 512>>>(bufC, bufA, N);
    bn_finalize_kernel<<<1, 32>>>(g3, be3, 192, invN);

    // ---- Layer 4: GCN(32->32); BN3 applied on GEMM load; b4 folded into pool ----
    gemm_small<32, 32, 8, 192><<<CDIV(N, 32), 128>>>(bufA, W4, bufC, N);
    gather32_kernel<0><<<CDIV(N * 32, 512), 512>>>(bufC, bufB, N);

    // ---- pool + link ----
    pool_kernel<<<CDIV(N * 8, 256), 256>>>(bufB, batch, b4, N);
    link_kernel<<<CDIV(L * 32, 256), 256>>>(li, out, L);
}

// round 6
// speedup vs baseline: 1.5677x; 1.1657x over previous
#include <cuda_runtime.h>
#include <math.h>

#define NMAX 50000
#define EMAX 800000
#define GMAX 1000
#define LEAK 0.01f
#define EPS  1e-5f
#define CDIV(a,b) (((a)+(b)-1)/(b))

// ---------------- scratch ----------------------------------------------------
__device__ float g_bufA[NMAX*128];
__device__ float g_bufB[NMAX*128];
__device__ float g_bufC[NMAX*128];
__device__ int   g_indeg[NMAX];
__device__ int   g_off[NMAX+1];
__device__ int   g_cur[NMAX];
__device__ int   g_csr[EMAX];
__device__ float g_dinv[NMAX];     // rsqrt(indeg+1)
__device__ float g_rcnt[NMAX];     // 1/max(indeg,1)
__device__ float g_colsum[256];    // L1:0..127  L2:128..191  L3:192..223
__device__ float g_colsq[256];
__device__ float g_scale[256];
__device__ float g_shift[256];
__device__ float g_pool[GMAX*32];

// ---------------- degree / CSR ----------------------------------------------
__global__ void deg_kernel(const int* __restrict__ dst, int nE) {
    int e = blockIdx.x * blockDim.x + threadIdx.x;
    if (e < nE) atomicAdd(&g_indeg[dst[e]], 1);
}

__global__ void scan_kernel(int n) {
    __shared__ int part[1024];
    int tid = threadIdx.x;
    int chunk = CDIV(n, 1024);
    int start = tid * chunk;
    int end   = min(start + chunk, n);
    int s = 0;
    for (int i = start; i < end; i++) s += g_indeg[i];
    part[tid] = s;
    __syncthreads();
    for (int off = 1; off < 1024; off <<= 1) {
        int v = (tid >= off) ? part[tid - off] : 0;
        __syncthreads();
        part[tid] += v;
        __syncthreads();
    }
    int run = (tid > 0) ? part[tid - 1] : 0;
    for (int i = start; i < end; i++) {
        int d = g_indeg[i];
        g_off[i] = run;
        g_cur[i] = run;
        g_dinv[i] = rsqrtf((float)(d + 1));
        g_rcnt[i] = 1.0f / (float)(d > 0 ? d : 1);
        run += d;
    }
    if (end == n && start < n) g_off[n] = run;
}

__global__ void fill_csr_kernel(const int* __restrict__ src,
                                const int* __restrict__ dst, int nE) {
    int e = blockIdx.x * blockDim.x + threadIdx.x;
    if (e < nE) {
        int p = atomicAdd(&g_cur[dst[e]], 1);
        g_csr[p] = src[e];
    }
}

// ---------------- GEMM1 (round-2 proven): Y = X@W1 * dinv[row], K=M=128 ------
// blockDim 128, 8 rows/block, thread owns one column.
__global__ void gemm1_kernel(const float* __restrict__ X, const float* __restrict__ W,
                             float* __restrict__ Y, int n) {
    const int K = 128, M = 128, BR = 8, PBR = 12;
    __shared__ float xs[K * PBR];
    int tid = threadIdx.x;
    int r0  = blockIdx.x * BR;
    for (int i = tid; i < BR * K; i += 128) {
        int r = i >> 7, k = i & 127;
        int row = r0 + r;
        xs[k * PBR + r] = (row < n) ? X[row * K + k] : 0.0f;
    }
    __syncthreads();
    float acc[BR];
#pragma unroll
    for (int r = 0; r < BR; r++) acc[r] = 0.0f;
#pragma unroll 4
    for (int k = 0; k < K; k++) {
        float w = W[k * M + tid];
        const float4* xv = (const float4*)&xs[k * PBR];
#pragma unroll
        for (int r4 = 0; r4 < BR / 4; r4++) {
            float4 xx = xv[r4];
            acc[r4*4+0] = fmaf(xx.x, w, acc[r4*4+0]);
            acc[r4*4+1] = fmaf(xx.y, w, acc[r4*4+1]);
            acc[r4*4+2] = fmaf(xx.z, w, acc[r4*4+2]);
            acc[r4*4+3] = fmaf(xx.w, w, acc[r4*4+3]);
        }
    }
#pragma unroll
    for (int r = 0; r < BR; r++) {
        int row = r0 + r;
        if (row < n) Y[row * M + tid] = acc[r] * g_dinv[row];
    }
}

// ---------------- dual GEMM: P = h@Wl, Q = h@Wr  with h = lrelu(bn1(X)) ------
// K=128, M=64; blockDim 128; 16 rows/block (2 row-groups of 8).
__global__ void dual_gemm_kernel(const float* __restrict__ X,
                                 const float* __restrict__ Wl, const float* __restrict__ Wr,
                                 float* __restrict__ P, float* __restrict__ Q, int n) {
    const int K = 128, M = 64, BR = 16, PBR = 20;
    __shared__ float xs[K * PBR];
    int tid = threadIdx.x;
    int r0  = blockIdx.x * BR;
    for (int i = tid; i < BR * K; i += 128) {
        int r = i >> 7, k = i & 127;
        int row = r0 + r;
        float v = (row < n) ? X[row * K + k] : 0.0f;
        v = fmaf(v, g_scale[k], g_shift[k]);
        v = (v >= 0.0f) ? v : LEAK * v;
        xs[k * PBR + r] = v;
    }
    __syncthreads();
    int col = tid & 63;
    int rg  = tid >> 6;
    float accP[8], accQ[8];
#pragma unroll
    for (int r = 0; r < 8; r++) { accP[r] = 0.0f; accQ[r] = 0.0f; }
#pragma unroll 2
    for (int k = 0; k < K; k++) {
        float wl = Wl[k * M + col];
        float wr = Wr[k * M + col];
        const float4* xv = (const float4*)&xs[k * PBR + rg * 8];
#pragma unroll
        for (int r4 = 0; r4 < 2; r4++) {
            float4 xx = xv[r4];
            accP[r4*4+0] = fmaf(xx.x, wl, accP[r4*4+0]);
            accQ[r4*4+0] = fmaf(xx.x, wr, accQ[r4*4+0]);
            accP[r4*4+1] = fmaf(xx.y, wl, accP[r4*4+1]);
            accQ[r4*4+1] = fmaf(xx.y, wr, accQ[r4*4+1]);
            accP[r4*4+2] = fmaf(xx.z, wl, accP[r4*4+2]);
            accQ[r4*4+2] = fmaf(xx.z, wr, accQ[r4*4+2]);
            accP[r4*4+3] = fmaf(xx.w, wl, accP[r4*4+3]);
            accQ[r4*4+3] = fmaf(xx.w, wr, accQ[r4*4+3]);
        }
    }
#pragma unroll
    for (int r = 0; r < 8; r++) {
        int row = r0 + rg * 8 + r;
        if (row < n) {
            P[row * M + col] = accP[r];
            Q[row * M + col] = accQ[r];
        }
    }
}

// ---------------- small GEMM (M=32): Y = lrelu(bn(X)) @ W, * dinv ------------
template <int K, int M, int ROWS, int OFF>
__global__ void gemm_small(const float* __restrict__ X, const float* __restrict__ W,
                           float* __restrict__ Y, int n) {
    const int RG  = 128 / M;
    const int BR  = RG * ROWS;
    const int PBR = BR + 4;
    __shared__ float xs[K * PBR];
    int tid = threadIdx.x;
    int r0  = blockIdx.x * BR;
    for (int i = tid; i < BR * K; i += 128) {
        int r = i / K, k = i % K;
        int row = r0 + r;
        float v = (row < n) ? X[row * K + k] : 0.0f;
        v = fmaf(v, g_scale[OFF + k], g_shift[OFF + k]);
        v = (v >= 0.0f) ? v : LEAK * v;
        xs[k * PBR + r] = v;
    }
    __syncthreads();
    int col = tid % M;
    int rg  = tid / M;
    float acc[ROWS];
#pragma unroll
    for (int r = 0; r < ROWS; r++) acc[r] = 0.0f;
#pragma unroll 4
    for (int k = 0; k < K; k++) {
        float w = W[k * M + col];
        const float4* xv = (const float4*)&xs[k * PBR + rg * ROWS];
#pragma unroll
        for (int r4 = 0; r4 < ROWS / 4; r4++) {
            float4 xx = xv[r4];
            acc[r4*4+0] = fmaf(xx.x, w, acc[r4*4+0]);
            acc[r4*4+1] = fmaf(xx.y, w, acc[r4*4+1]);
            acc[r4*4+2] = fmaf(xx.z, w, acc[r4*4+2]);
            acc[r4*4+3] = fmaf(xx.w, w, acc[r4*4+3]);
        }
    }
#pragma unroll
    for (int r = 0; r < ROWS; r++) {
        int row = r0 + rg * ROWS + r;
        if (row < n) Y[row * M + col] = acc[r] * g_dinv[row];
    }
}

// ---------------- CSR gathers ------------------------------------------------
// GCN gather F=128 (round-2 proven): acc init = self (pre-scaled), out *= dinv.
__global__ void gather128_gcn(const float* __restrict__ Hin, float* __restrict__ Hout,
                              int n) {
    int warp = (blockIdx.x * blockDim.x + threadIdx.x) >> 5;
    int lane = threadIdx.x & 31;
    if (warp >= n) return;
    int beg = g_off[warp], end = g_off[warp + 1];
    const float4* H4 = (const float4*)Hin;
    float4 acc = H4[warp * 32 + lane];
#pragma unroll 4
    for (int e = beg; e < end; e++) {
        int s = __ldg(&g_csr[e]);
        float4 v = H4[s * 32 + lane];
        acc.x += v.x; acc.y += v.y; acc.z += v.z; acc.w += v.w;
    }
    float sc = g_dinv[warp];
    acc.x *= sc; acc.y *= sc; acc.z *= sc; acc.w *= sc;
    ((float4*)Hout)[warp * 32 + lane] = acc;
}

// SAGE gather F=64 over P, + Q: Y = rcnt * sum(P[nbrs]) + Q.  warp/node, float2/lane.
__global__ void gather64_sage(const float* __restrict__ P, const float* __restrict__ Q,
                              float* __restrict__ Y, int n) {
    int warp = (blockIdx.x * blockDim.x + threadIdx.x) >> 5;
    int lane = threadIdx.x & 31;
    if (warp >= n) return;
    int beg = g_off[warp], end = g_off[warp + 1];
    const float2* P2 = (const float2*)P;
    float2 acc = make_float2(0.f, 0.f);
#pragma unroll 4
    for (int e = beg; e < end; e++) {
        int s = __ldg(&g_csr[e]);
        float2 v = P2[s * 32 + lane];
        acc.x += v.x; acc.y += v.y;
    }
    float r = g_rcnt[warp];
    float2 q = ((const float2*)Q)[warp * 32 + lane];
    acc.x = fmaf(acc.x, r, q.x);
    acc.y = fmaf(acc.y, r, q.y);
    ((float2*)Y)[warp * 32 + lane] = acc;
}

// F=32 GCN gather.
__global__ void gather32_kernel(const float* __restrict__ Hin,
                                float* __restrict__ Hout, int n) {
    int warp = (blockIdx.x * blockDim.x + threadIdx.x) >> 5;
    int lane = threadIdx.x & 31;
    if (warp >= n) return;
    int beg = g_off[warp], end = g_off[warp + 1];
    float acc = Hin[warp * 32 + lane];
#pragma unroll 4
    for (int e = beg; e < end; e++) {
        int s = __ldg(&g_csr[e]);
        acc += Hin[s * 32 + lane];
    }
    Hout[warp * 32 + lane] = acc * g_dinv[warp];
}

// ---------------- batch norm (round-2 proven) --------------------------------
template <int C, int OFF>
__global__ void bn_stats_kernel(const float* __restrict__ X, long long total) {
    __shared__ float s1[256];
    __shared__ float s2[256];
    int tid = threadIdx.x;
    float sum = 0.0f, sq = 0.0f;
    for (long long i = (long long)blockIdx.x * 256 + tid; i < total;
         i += (long long)gridDim.x * 256) {
        float v = X[i];
        sum += v; sq += v * v;
    }
    s1[tid] = sum; s2[tid] = sq;
    __syncthreads();
    for (int off = 128; off >= C; off >>= 1) {
        if (tid < off) { s1[tid] += s1[tid + off]; s2[tid] += s2[tid + off]; }
        __syncthreads();
    }
    if (tid < C) {
        atomicAdd(&g_colsum[OFF + tid], s1[tid]);
        atomicAdd(&g_colsq[OFF + tid],  s2[tid]);
    }
}

__global__ void bn_finalize_kernel(const float* __restrict__ gamma,
                                   const float* __restrict__ beta, int off, float invn) {
    int c = threadIdx.x;
    float m   = g_colsum[off + c] * invn;
    float var = g_colsq[off + c] * invn - m * m;
    float sc  = gamma[c] * rsqrtf(var + EPS);
    g_scale[off + c] = sc;
    g_shift[off + c] = beta[c] - m * sc;
}

// ---------------- pool + link ------------------------------------------------
__global__ void pool_kernel(const float* __restrict__ H, const int* __restrict__ batch,
                            const float* __restrict__ b4, int n) {
    int t = blockIdx.x * blockDim.x + threadIdx.x;
    int node = t / 8, j = t % 8;
    if (node >= n) return;
    int g = batch[node];
    float4 v = ((const float4*)H)[node * 8 + j];
    float4 bb = ((const float4*)b4)[j];
    v.x += bb.x; v.y += bb.y; v.z += bb.z; v.w += bb.w;
    float4* p = ((float4*)g_pool) + g * 8 + j;
    asm volatile("red.global.add.v4.f32 [%0], {%1,%2,%3,%4};"
                 :: "l"(p), "f"(v.x), "f"(v.y), "f"(v.z), "f"(v.w) : "memory");
}

__global__ void link_kernel(const int* __restrict__ li, float* __restrict__ out, int L) {
    int w = (blockIdx.x * blockDim.x + threadIdx.x) / 32;
    int lane = threadIdx.x & 31;
    if (w >= L) return;
    int a = li[w], b = li[L + w];
    float v = g_pool[a * 32 + lane] * g_pool[b * 32 + lane];
#pragma unroll
    for (int off = 16; off > 0; off >>= 1)
        v += __shfl_xor_sync(0xFFFFFFFFu, v, off);
    if (lane == 0) out[w] = 1.0f / (1.0f + expf(-v));
}

// ---------------- launch -----------------------------------------------------
extern "C" void kernel_launch(void* const* d_in, const int* in_sizes, int n_in,
                              void* d_out, int out_size) {
    int base = 4;
    if (n_in >= 20 && in_sizes[4] == 1) base = 5;

    const float* x    = (const float*)d_in[0];
    const int*   ei   = (const int*)d_in[1];
    const int*   batch= (const int*)d_in[2];
    const int*   li   = (const int*)d_in[3];
    const float* W1   = (const float*)d_in[base + 0];
    const float* g1   = (const float*)d_in[base + 2];
    const float* be1  = (const float*)d_in[base + 3];
    const float* Wl2  = (const float*)d_in[base + 4];
    const float* Wr2  = (const float*)d_in[base + 6];
    const float* g2   = (const float*)d_in[base + 7];
    const float* be2  = (const float*)d_in[base + 8];
    const float* W3   = (const float*)d_in[base + 9];
    const float* g3   = (const float*)d_in[base + 11];
    const float* be3  = (const float*)d_in[base + 12];
    const float* W4   = (const float*)d_in[base + 13];
    const float* b4   = (const float*)d_in[base + 14];
    float* out = (float*)d_out;

    const int N = in_sizes[0] / 128;
    const int E = in_sizes[1] / 2;
    const int L = in_sizes[3] / 2;
    const int* src = ei;
    const int* dst = ei + E;
    const float invN = 1.0f / (float)N;

    float *bufA, *bufB, *bufC, *poolp, *colsum, *colsq;
    int* indeg;
    cudaGetSymbolAddress((void**)&bufA,   g_bufA);
    cudaGetSymbolAddress((void**)&bufB,   g_bufB);
    cudaGetSymbolAddress((void**)&bufC,   g_bufC);
    cudaGetSymbolAddress((void**)&indeg,  g_indeg);
    cudaGetSymbolAddress((void**)&poolp,  g_pool);
    cudaGetSymbolAddress((void**)&colsum, g_colsum);
    cudaGetSymbolAddress((void**)&colsq,  g_colsq);

    // ---- setup ----
    cudaMemsetAsync(indeg,  0, N * sizeof(int));
    cudaMemsetAsync(colsum, 0, 256 * sizeof(float));
    cudaMemsetAsync(colsq,  0, 256 * sizeof(float));
    cudaMemsetAsync(poolp,  0, (size_t)GMAX * 32 * sizeof(float));
    deg_kernel<<<CDIV(E, 256), 256>>>(dst, E);
    scan_kernel<<<1, 1024>>>(N);
    fill_csr_kernel<<<CDIV(E, 256), 256>>>(src, dst, E);

    // ---- Layer 1: GCN(128->128) ----
    gemm1_kernel<<<CDIV(N, 8), 128>>>(x, W1, bufA, N);               // x@W1 * dinv
    gather128_gcn<<<CDIV(N * 32, 256), 256>>>(bufA, bufB, N);        // raw gcn1 -> bufB
    bn_stats_kernel<128, 0><<<1024, 256>>>(bufB, (long long)N * 128);
    bn_finalize_kernel<<<1, 128>>>(g1, be1, 0, invN);

    // ---- Layer 2: SAGE(128->64), aggregation commuted past the GEMM ----
    // P = h1@Wl (bufA), Q = h1@Wr (bufC); h1 = lrelu(bn1(bufB)) applied on load
    dual_gemm_kernel<<<CDIV(N, 16), 128>>>(bufB, Wl2, Wr2, bufA, bufC, N);
    gather64_sage<<<CDIV(N * 32, 256), 256>>>(bufA, bufC, bufB, N);  // y2 -> bufB
    bn_stats_kernel<64, 128><<<1024, 256>>>(bufB, (long long)N * 64);
    bn_finalize_kernel<<<1, 64>>>(g2, be2, 128, invN);

    // ---- Layer 3: GCN(64->32); BN2 applied on GEMM load ----
    gemm_small<64, 32, 8, 128><<<CDIV(N, 32), 128>>>(bufB, W3, bufA, N);
    gather32_kernel<<<CDIV(N * 32, 256), 256>>>(bufA, bufC, N);      // raw gcn3 -> bufC
    bn_stats_kernel<32, 192><<<1024, 256>>>(bufC, (long long)N * 32);
    bn_finalize_kernel<<<1, 32>>>(g3, be3, 192, invN);

    // ---- Layer 4: GCN(32->32); BN3 applied on GEMM load; b4 folded into pool ----
    gemm_small<32, 32, 8, 192><<<CDIV(N, 32), 128>>>(bufC, W4, bufA, N);
    gather32_kernel<<<CDIV(N * 32, 256), 256>>>(bufA, bufB, N);

    // ---- pool + link ----
    pool_kernel<<<CDIV(N * 8, 256), 256>>>(bufB, batch, b4, N);
    link_kernel<<<CDIV(L * 32, 256), 256>>>(li, out, L);
}

// round 7
// speedup vs baseline: 1.5776x; 1.0063x over previous
#include <cuda_runtime.h>
#include <cuda_fp16.h>
#include <math.h>

#define NMAX 50000
#define EMAX 800000
#define GMAX 1000
#define LEAK 0.01f
#define EPS  1e-5f
#define CDIV(a,b) (((a)+(b)-1)/(b))

// ---------------- scratch ----------------------------------------------------
__device__ float g_bufA[NMAX*128];
__device__ float g_bufB[NMAX*128];
__device__ float g_bufC[NMAX*128];
__device__ int   g_indeg[NMAX];
__device__ int   g_off[NMAX+1];
__device__ int   g_cur[NMAX];
__device__ int   g_csr[EMAX];
__device__ float g_dinv[NMAX];     // rsqrt(indeg+1)
__device__ float g_rcnt[NMAX];     // 1/max(indeg,1)
__device__ float g_colsum[256];    // L1:0..127  L2:128..191  L3:192..223
__device__ float g_colsq[256];
__device__ float g_scale[256];
__device__ float g_shift[256];
__device__ float g_pool[GMAX*32];

// ---------------- degree / CSR ----------------------------------------------
__global__ void deg_kernel(const int* __restrict__ dst, int nE) {
    int e = blockIdx.x * blockDim.x + threadIdx.x;
    if (e < nE) atomicAdd(&g_indeg[dst[e]], 1);
}

__global__ void scan_kernel(int n) {
    __shared__ int part[1024];
    int tid = threadIdx.x;
    int chunk = CDIV(n, 1024);
    int start = tid * chunk;
    int end   = min(start + chunk, n);
    int s = 0;
    for (int i = start; i < end; i++) s += g_indeg[i];
    part[tid] = s;
    __syncthreads();
    for (int off = 1; off < 1024; off <<= 1) {
        int v = (tid >= off) ? part[tid - off] : 0;
        __syncthreads();
        part[tid] += v;
        __syncthreads();
    }
    int run = (tid > 0) ? part[tid - 1] : 0;
    for (int i = start; i < end; i++) {
        int d = g_indeg[i];
        g_off[i] = run;
        g_cur[i] = run;
        g_dinv[i] = rsqrtf((float)(d + 1));
        g_rcnt[i] = 1.0f / (float)(d > 0 ? d : 1);
        run += d;
    }
    if (end == n && start < n) g_off[n] = run;
}

__global__ void fill_csr_kernel(const int* __restrict__ src,
                                const int* __restrict__ dst, int nE) {
    int e = blockIdx.x * blockDim.x + threadIdx.x;
    if (e < nE) {
        int p = atomicAdd(&g_cur[dst[e]], 1);
        g_csr[p] = src[e];
    }
}

// ---------------- GEMM1: Yh[n,128] = half(X@W1 * dinv[row]) ------------------
__global__ void gemm1_kernel(const float* __restrict__ X, const float* __restrict__ W,
                             __half* __restrict__ Yh, int n) {
    const int K = 128, M = 128, BR = 8, PBR = 12;
    __shared__ float xs[K * PBR];
    int tid = threadIdx.x;
    int r0  = blockIdx.x * BR;
    for (int i = tid; i < BR * K; i += 128) {
        int r = i >> 7, k = i & 127;
        int row = r0 + r;
        xs[k * PBR + r] = (row < n) ? X[row * K + k] : 0.0f;
    }
    __syncthreads();
    float acc[BR];
#pragma unroll
    for (int r = 0; r < BR; r++) acc[r] = 0.0f;
#pragma unroll 4
    for (int k = 0; k < K; k++) {
        float w = W[k * M + tid];
        const float4* xv = (const float4*)&xs[k * PBR];
#pragma unroll
        for (int r4 = 0; r4 < BR / 4; r4++) {
            float4 xx = xv[r4];
            acc[r4*4+0] = fmaf(xx.x, w, acc[r4*4+0]);
            acc[r4*4+1] = fmaf(xx.y, w, acc[r4*4+1]);
            acc[r4*4+2] = fmaf(xx.z, w, acc[r4*4+2]);
            acc[r4*4+3] = fmaf(xx.w, w, acc[r4*4+3]);
        }
    }
#pragma unroll
    for (int r = 0; r < BR; r++) {
        int row = r0 + r;
        if (row < n) Yh[row * M + tid] = __float2half_rn(acc[r] * g_dinv[row]);
    }
}

// ---------------- dual GEMM: P(half) = h@Wl, Q(fp32) = h@Wr ------------------
// h = lrelu(bn1(X)). K=128, M=64; blockDim 128; 16 rows/block.
__global__ void dual_gemm_kernel(const float* __restrict__ X,
                                 const float* __restrict__ Wl, const float* __restrict__ Wr,
                                 __half* __restrict__ P, float* __restrict__ Q, int n) {
    const int K = 128, M = 64, BR = 16, PBR = 20;
    __shared__ float xs[K * PBR];
    int tid = threadIdx.x;
    int r0  = blockIdx.x * BR;
    for (int i = tid; i < BR * K; i += 128) {
        int r = i >> 7, k = i & 127;
        int row = r0 + r;
        float v = (row < n) ? X[row * K + k] : 0.0f;
        v = fmaf(v, g_scale[k], g_shift[k]);
        v = (v >= 0.0f) ? v : LEAK * v;
        xs[k * PBR + r] = v;
    }
    __syncthreads();
    int col = tid & 63;
    int rg  = tid >> 6;
    float accP[8], accQ[8];
#pragma unroll
    for (int r = 0; r < 8; r++) { accP[r] = 0.0f; accQ[r] = 0.0f; }
#pragma unroll 2
    for (int k = 0; k < K; k++) {
        float wl = Wl[k * M + col];
        float wr = Wr[k * M + col];
        const float4* xv = (const float4*)&xs[k * PBR + rg * 8];
#pragma unroll
        for (int r4 = 0; r4 < 2; r4++) {
            float4 xx = xv[r4];
            accP[r4*4+0] = fmaf(xx.x, wl, accP[r4*4+0]);
            accQ[r4*4+0] = fmaf(xx.x, wr, accQ[r4*4+0]);
            accP[r4*4+1] = fmaf(xx.y, wl, accP[r4*4+1]);
            accQ[r4*4+1] = fmaf(xx.y, wr, accQ[r4*4+1]);
            accP[r4*4+2] = fmaf(xx.z, wl, accP[r4*4+2]);
            accQ[r4*4+2] = fmaf(xx.z, wr, accQ[r4*4+2]);
            accP[r4*4+3] = fmaf(xx.w, wl, accP[r4*4+3]);
            accQ[r4*4+3] = fmaf(xx.w, wr, accQ[r4*4+3]);
        }
    }
#pragma unroll
    for (int r = 0; r < 8; r++) {
        int row = r0 + rg * 8 + r;
        if (row < n) {
            P[row * M + col] = __float2half_rn(accP[r]);
            Q[row * M + col] = accQ[r];
        }
    }
}

// ---------------- small GEMM (M=32): Y = lrelu(bn(X)) @ W, * dinv ------------
template <int K, int M, int ROWS, int OFF>
__global__ void gemm_small(const float* __restrict__ X, const float* __restrict__ W,
                           float* __restrict__ Y, int n) {
    const int RG  = 128 / M;
    const int BR  = RG * ROWS;
    const int PBR = BR + 4;
    __shared__ float xs[K * PBR];
    int tid = threadIdx.x;
    int r0  = blockIdx.x * BR;
    for (int i = tid; i < BR * K; i += 128) {
        int r = i / K, k = i % K;
        int row = r0 + r;
        float v = (row < n) ? X[row * K + k] : 0.0f;
        v = fmaf(v, g_scale[OFF + k], g_shift[OFF + k]);
        v = (v >= 0.0f) ? v : LEAK * v;
        xs[k * PBR + r] = v;
    }
    __syncthreads();
    int col = tid % M;
    int rg  = tid / M;
    float acc[ROWS];
#pragma unroll
    for (int r = 0; r < ROWS; r++) acc[r] = 0.0f;
#pragma unroll 4
    for (int k = 0; k < K; k++) {
        float w = W[k * M + col];
        const float4* xv = (const float4*)&xs[k * PBR + rg * ROWS];
#pragma unroll
        for (int r4 = 0; r4 < ROWS / 4; r4++) {
            float4 xx = xv[r4];
            acc[r4*4+0] = fmaf(xx.x, w, acc[r4*4+0]);
            acc[r4*4+1] = fmaf(xx.y, w, acc[r4*4+1]);
            acc[r4*4+2] = fmaf(xx.z, w, acc[r4*4+2]);
            acc[r4*4+3] = fmaf(xx.w, w, acc[r4*4+3]);
        }
    }
#pragma unroll
    for (int r = 0; r < ROWS; r++) {
        int row = r0 + rg * ROWS + r;
        if (row < n) Y[row * M + col] = acc[r] * g_dinv[row];
    }
}

// ---------------- CSR gathers ------------------------------------------------
// GCN gather F=128 over fp16 rows (256B each): lane owns feats 4*lane..+3.
__global__ void gather128_gcn_h(const __half* __restrict__ Hin,
                                float* __restrict__ Hout, int n) {
    int warp = (blockIdx.x * blockDim.x + threadIdx.x) >> 5;
    int lane = threadIdx.x & 31;
    if (warp >= n) return;
    int beg = g_off[warp], end = g_off[warp + 1];
    const uint2* H2 = (const uint2*)Hin;         // 8B = 4 halfs per lane
    uint2 raw = H2[warp * 32 + lane];            // self (pre-scaled by dinv)
    const __half2* hp = (const __half2*)&raw;
    float2 a0 = __half22float2(hp[0]);
    float2 a1 = __half22float2(hp[1]);
    float4 acc = make_float4(a0.x, a0.y, a1.x, a1.y);
#pragma unroll 4
    for (int e = beg; e < end; e++) {
        int s = __ldg(&g_csr[e]);
        uint2 r2 = H2[s * 32 + lane];
        const __half2* rp = (const __half2*)&r2;
        float2 b0 = __half22float2(rp[0]);
        float2 b1 = __half22float2(rp[1]);
        acc.x += b0.x; acc.y += b0.y; acc.z += b1.x; acc.w += b1.y;
    }
    float sc = g_dinv[warp];
    acc.x *= sc; acc.y *= sc; acc.z *= sc; acc.w *= sc;
    ((float4*)Hout)[warp * 32 + lane] = acc;
}

// SAGE gather F=64 over fp16 P (+ fp32 Q): lane owns feats 2*lane..+1.
__global__ void gather64_sage_h(const __half* __restrict__ P, const float* __restrict__ Q,
                                float* __restrict__ Y, int n) {
    int warp = (blockIdx.x * blockDim.x + threadIdx.x) >> 5;
    int lane = threadIdx.x & 31;
    if (warp >= n) return;
    int beg = g_off[warp], end = g_off[warp + 1];
    const __half2* P2 = (const __half2*)P;       // 4B = 2 halfs per lane
    float2 acc = make_float2(0.f, 0.f);
#pragma unroll 4
    for (int e = beg; e < end; e++) {
        int s = __ldg(&g_csr[e]);
        float2 v = __half22float2(P2[s * 32 + lane]);
        acc.x += v.x; acc.y += v.y;
    }
    float r = g_rcnt[warp];
    float2 q = ((const float2*)Q)[warp * 32 + lane];
    acc.x = fmaf(acc.x, r, q.x);
    acc.y = fmaf(acc.y, r, q.y);
    ((float2*)Y)[warp * 32 + lane] = acc;
}

// F=32 GCN gather (fp32).
__global__ void gather32_kernel(const float* __restrict__ Hin,
                                float* __restrict__ Hout, int n) {
    int warp = (blockIdx.x * blockDim.x + threadIdx.x) >> 5;
    int lane = threadIdx.x & 31;
    if (warp >= n) return;
    int beg = g_off[warp], end = g_off[warp + 1];
    float acc = Hin[warp * 32 + lane];
#pragma unroll 4
    for (int e = beg; e < end; e++) {
        int s = __ldg(&g_csr[e]);
        acc += Hin[s * 32 + lane];
    }
    Hout[warp * 32 + lane] = acc * g_dinv[warp];
}

// ---------------- batch norm -------------------------------------------------
template <int C, int OFF>
__global__ void bn_stats_kernel(const float* __restrict__ X, long long total) {
    __shared__ float s1[256];
    __shared__ float s2[256];
    int tid = threadIdx.x;
    float sum = 0.0f, sq = 0.0f;
    for (long long i = (long long)blockIdx.x * 256 + tid; i < total;
         i += (long long)gridDim.x * 256) {
        float v = X[i];
        sum += v; sq += v * v;
    }
    s1[tid] = sum; s2[tid] = sq;
    __syncthreads();
    for (int off = 128; off >= C; off >>= 1) {
        if (tid < off) { s1[tid] += s1[tid + off]; s2[tid] += s2[tid + off]; }
        __syncthreads();
    }
    if (tid < C) {
        atomicAdd(&g_colsum[OFF + tid], s1[tid]);
        atomicAdd(&g_colsq[OFF + tid],  s2[tid]);
    }
}

__global__ void bn_finalize_kernel(const float* __restrict__ gamma,
                                   const float* __restrict__ beta, int off, float invn) {
    int c = threadIdx.x;
    float m   = g_colsum[off + c] * invn;
    float var = g_colsq[off + c] * invn - m * m;
    float sc  = gamma[c] * rsqrtf(var + EPS);
    g_scale[off + c] = sc;
    g_shift[off + c] = beta[c] - m * sc;
}

// ---------------- pool + link ------------------------------------------------
__global__ void pool_kernel(const float* __restrict__ H, const int* __restrict__ batch,
                            const float* __restrict__ b4, int n) {
    int t = blockIdx.x * blockDim.x + threadIdx.x;
    int node = t / 8, j = t % 8;
    if (node >= n) return;
    int g = batch[node];
    float4 v = ((const float4*)H)[node * 8 + j];
    float4 bb = ((const float4*)b4)[j];
    v.x += bb.x; v.y += bb.y; v.z += bb.z; v.w += bb.w;
    float4* p = ((float4*)g_pool) + g * 8 + j;
    asm volatile("red.global.add.v4.f32 [%0], {%1,%2,%3,%4};"
                 :: "l"(p), "f"(v.x), "f"(v.y), "f"(v.z), "f"(v.w) : "memory");
}

__global__ void link_kernel(const int* __restrict__ li, float* __restrict__ out, int L) {
    int w = (blockIdx.x * blockDim.x + threadIdx.x) / 32;
    int lane = threadIdx.x & 31;
    if (w >= L) return;
    int a = li[w], b = li[L + w];
    float v = g_pool[a * 32 + lane] * g_pool[b * 32 + lane];
#pragma unroll
    for (int off = 16; off > 0; off >>= 1)
        v += __shfl_xor_sync(0xFFFFFFFFu, v, off);
    if (lane == 0) out[w] = 1.0f / (1.0f + expf(-v));
}

// ---------------- launch -----------------------------------------------------
extern "C" void kernel_launch(void* const* d_in, const int* in_sizes, int n_in,
                              void* d_out, int out_size) {
    int base = 4;
    if (n_in >= 20 && in_sizes[4] == 1) base = 5;

    const float* x    = (const float*)d_in[0];
    const int*   ei   = (const int*)d_in[1];
    const int*   batch= (const int*)d_in[2];
    const int*   li   = (const int*)d_in[3];
    const float* W1   = (const float*)d_in[base + 0];
    const float* g1   = (const float*)d_in[base + 2];
    const float* be1  = (const float*)d_in[base + 3];
    const float* Wl2  = (const float*)d_in[base + 4];
    const float* Wr2  = (const float*)d_in[base + 6];
    const float* g2   = (const float*)d_in[base + 7];
    const float* be2  = (const float*)d_in[base + 8];
    const float* W3   = (const float*)d_in[base + 9];
    const float* g3   = (const float*)d_in[base + 11];
    const float* be3  = (const float*)d_in[base + 12];
    const float* W4   = (const float*)d_in[base + 13];
    const float* b4   = (const float*)d_in[base + 14];
    float* out = (float*)d_out;

    const int N = in_sizes[0] / 128;
    const int E = in_sizes[1] / 2;
    const int L = in_sizes[3] / 2;
    const int* src = ei;
    const int* dst = ei + E;
    const float invN = 1.0f / (float)N;

    float *bufA, *bufB, *bufC, *poolp, *colsum, *colsq;
    int* indeg;
    cudaGetSymbolAddress((void**)&bufA,   g_bufA);
    cudaGetSymbolAddress((void**)&bufB,   g_bufB);
    cudaGetSymbolAddress((void**)&bufC,   g_bufC);
    cudaGetSymbolAddress((void**)&indeg,  g_indeg);
    cudaGetSymbolAddress((void**)&poolp,  g_pool);
    cudaGetSymbolAddress((void**)&colsum, g_colsum);
    cudaGetSymbolAddress((void**)&colsq,  g_colsq);
    __half* bufAh = (__half*)bufA;

    // ---- setup ----
    cudaMemsetAsync(indeg,  0, N * sizeof(int));
    cudaMemsetAsync(colsum, 0, 256 * sizeof(float));
    cudaMemsetAsync(colsq,  0, 256 * sizeof(float));
    cudaMemsetAsync(poolp,  0, (size_t)GMAX * 32 * sizeof(float));
    deg_kernel<<<CDIV(E, 256), 256>>>(dst, E);
    scan_kernel<<<1, 1024>>>(N);
    fill_csr_kernel<<<CDIV(E, 256), 256>>>(src, dst, E);

    // ---- Layer 1: GCN(128->128), fp16 intermediate for the gather ----
    gemm1_kernel<<<CDIV(N, 8), 128>>>(x, W1, bufAh, N);              // half(x@W1 * dinv)
    gather128_gcn_h<<<CDIV(N * 32, 256), 256>>>(bufAh, bufB, N);     // raw gcn1 -> bufB (fp32)
    bn_stats_kernel<128, 0><<<1024, 256>>>(bufB, (long long)N * 128);
    bn_finalize_kernel<<<1, 128>>>(g1, be1, 0, invN);

    // ---- Layer 2: SAGE(128->64), aggregation commuted past the GEMM ----
    // P = half(h1@Wl) -> bufAh, Q = h1@Wr -> bufC; h1 = lrelu(bn1(bufB)) on load
    dual_gemm_kernel<<<CDIV(N, 16), 128>>>(bufB, Wl2, Wr2, bufAh, bufC, N);
    gather64_sage_h<<<CDIV(N * 32, 256), 256>>>(bufAh, bufC, bufB, N);  // y2 -> bufB
    bn_stats_kernel<64, 128><<<1024, 256>>>(bufB, (long long)N * 64);
    bn_finalize_kernel<<<1, 64>>>(g2, be2, 128, invN);

    // ---- Layer 3: GCN(64->32); BN2 applied on GEMM load ----
    gemm_small<64, 32, 8, 128><<<CDIV(N, 32), 128>>>(bufB, W3, bufA, N);
    gather32_kernel<<<CDIV(N * 32, 256), 256>>>(bufA, bufC, N);      // raw gcn3 -> bufC
    bn_stats_kernel<32, 192><<<1024, 256>>>(bufC, (long long)N * 32);
    bn_finalize_kernel<<<1, 32>>>(g3, be3, 192, invN);

    // ---- Layer 4: GCN(32->32); BN3 applied on GEMM load; b4 folded into pool ----
    gemm_small<32, 32, 8, 192><<<CDIV(N, 32), 128>>>(bufC, W4, bufA, N);
    gather32_kernel<<<CDIV(N * 32, 256), 256>>>(bufA, bufB, N);

    // ---- pool + link ----
    pool_kernel<<<CDIV(N * 8, 256), 256>>>(bufB, batch, b4, N);
    link_kernel<<<CDIV(L * 32, 256), 256>>>(li, out, L);
}